// round 1
// baseline (speedup 1.0000x reference)
#include <cuda_runtime.h>

// composed_loss_function: single-pass streaming reduction over N=1e6 rows.
// total = rrs_error + 10*obs_error + DK + l2_norm
//   rrs_error = sum_{n,i} w[i]*(rrs-rrs_pred)^2 / (5n),  w = 1/se_diag^2 (diag inverse)
//   obs_error = sum_n ( sum_i (pred-Yobs)^2 ) / lens_n / n   (Y_cov_inv = I)
//   lens_n    = count of non-NaN in nan_array row
//   DK        = 0.5*sum_n(logdet(4.9 I) - log det(cov_z_n) + tr(cov_z_n)/4.9)/n
//             + 0.5*sum_n |mu_z_n - MU|^2 / (4.9 * 3n)
//   l2_norm   = mean((parameters-1)^2)   (written into d_out by init kernel)

#define MU_PRIOR   0.6447f
#define LOGDET_SA  4.76770561517f   // 3*log(4.9)
#define INV49      (1.0f/4.9f)

__global__ void init_out_kernel(const float* __restrict__ params,
                                float* __restrict__ out, int np) {
    __shared__ float warp_sums[4];
    int t = threadIdx.x;
    float v = 0.f;
    for (int i = t; i < np; i += blockDim.x) {
        float d = params[i] - 1.f;
        v += d * d;
    }
    #pragma unroll
    for (int o = 16; o > 0; o >>= 1) v += __shfl_down_sync(0xffffffffu, v, o);
    if ((t & 31) == 0) warp_sums[t >> 5] = v;
    __syncthreads();
    if (t == 0) {
        float tot = 0.f;
        int nw = (blockDim.x + 31) >> 5;
        for (int i = 0; i < nw; i++) tot += warp_sums[i];
        out[0] = tot / (float)np;
    }
}

__global__ void __launch_bounds__(256)
loss_kernel(const float4* __restrict__ pred,  const float4* __restrict__ yobs,
            const float4* __restrict__ rrs,   const float4* __restrict__ rrsp,
            const float4* __restrict__ nana,  const float4* __restrict__ cov,
            const float4* __restrict__ mu,
            float* __restrict__ out,
            int ngroups_full, int rem,
            float s_rrs, float s_obs, float s_dk, float s_mu)
{
    // diag-inverse weights: 1/se^2
    const float w0 = 1.0f / (0.0015f  * 0.0015f);
    const float w1 = 1.0f / (0.0012f  * 0.0012f);
    const float w2 = 1.0f / (0.001f   * 0.001f);
    const float w3 = 1.0f / (0.00086f * 0.00086f);
    const float w4 = 1.0f / (0.00057f * 0.00057f);
    const float wtab[5] = {w0, w1, w2, w3, w4};

    int gid = blockIdx.x * blockDim.x + threadIdx.x;
    float tot = 0.f;

    if (gid < ngroups_full) {
        // --- group of 4 consecutive rows, all float4-aligned ---
        const int b9 = gid * 9;   // pred/yobs/nan/cov: 36 floats = 9 float4
        const int b5 = gid * 5;   // rrs/rrs_pred: 20 floats = 5 float4
        const int b3 = gid * 3;   // mu_z: 12 floats = 3 float4

        // ---- rrs weighted SSQ (flat: element e -> column e%5) ----
        float accr = 0.f;
        #pragma unroll
        for (int i = 0; i < 5; i++) {
            float4 a = rrs[b5 + i];
            float4 b = rrsp[b5 + i];
            float d;
            d = a.x - b.x; accr += wtab[(4*i + 0) % 5] * d * d;
            d = a.y - b.y; accr += wtab[(4*i + 1) % 5] * d * d;
            d = a.z - b.z; accr += wtab[(4*i + 2) % 5] * d * d;
            d = a.w - b.w; accr += wtab[(4*i + 3) % 5] * d * d;
        }

        // ---- pred/yobs SSQ per row + nan counts per row ----
        float rs[4] = {0.f, 0.f, 0.f, 0.f};
        float ln[4] = {0.f, 0.f, 0.f, 0.f};
        #pragma unroll
        for (int i = 0; i < 9; i++) {
            float4 p = pred[b9 + i];
            float4 q = yobs[b9 + i];
            float4 z = nana[b9 + i];
            float d;
            d = p.x - q.x; rs[(4*i + 0) / 9] += d * d; ln[(4*i + 0) / 9] += (z.x == z.x) ? 1.f : 0.f;
            d = p.y - q.y; rs[(4*i + 1) / 9] += d * d; ln[(4*i + 1) / 9] += (z.y == z.y) ? 1.f : 0.f;
            d = p.z - q.z; rs[(4*i + 2) / 9] += d * d; ln[(4*i + 2) / 9] += (z.z == z.z) ? 1.f : 0.f;
            d = p.w - q.w; rs[(4*i + 3) / 9] += d * d; ln[(4*i + 3) / 9] += (z.w == z.w) ? 1.f : 0.f;
        }
        float acco = 0.f;
        #pragma unroll
        for (int r = 0; r < 4; r++) acco += __fdividef(rs[r], ln[r]);

        // ---- cov_z: log det + trace per row ----
        float c[36];
        #pragma unroll
        for (int i = 0; i < 9; i++) {
            float4 v = cov[b9 + i];
            c[4*i + 0] = v.x; c[4*i + 1] = v.y; c[4*i + 2] = v.z; c[4*i + 3] = v.w;
        }
        float accd = 0.f;
        #pragma unroll
        for (int r = 0; r < 4; r++) {
            float m0 = c[r*9 + 0], m1 = c[r*9 + 1], m2 = c[r*9 + 2];
            float m3 = c[r*9 + 3], m4 = c[r*9 + 4], m5 = c[r*9 + 5];
            float m6 = c[r*9 + 6], m7 = c[r*9 + 7], m8 = c[r*9 + 8];
            float tr  = m0 + m4 + m8;
            float det = m0 * (m4*m8 - m5*m7)
                      - m1 * (m3*m8 - m5*m6)
                      + m2 * (m3*m7 - m4*m6);
            accd += (LOGDET_SA - __logf(det)) + tr * INV49;
        }

        // ---- mu_z SSQ around prior ----
        float mm[12];
        #pragma unroll
        for (int i = 0; i < 3; i++) {
            float4 v = mu[b3 + i];
            mm[4*i + 0] = v.x; mm[4*i + 1] = v.y; mm[4*i + 2] = v.z; mm[4*i + 3] = v.w;
        }
        float accm = 0.f;
        #pragma unroll
        for (int e = 0; e < 12; e++) {
            float d = mm[e] - MU_PRIOR;
            accm += d * d;
        }

        tot = accr * s_rrs + acco * s_obs + accd * s_dk + accm * s_mu;
    } else if (rem > 0 && gid == ngroups_full) {
        // --- scalar tail: rows [4*ngroups_full, 4*ngroups_full + rem) ---
        const float* predf = (const float*)pred;
        const float* yobsf = (const float*)yobs;
        const float* rrsf  = (const float*)rrs;
        const float* rrspf = (const float*)rrsp;
        const float* nanf  = (const float*)nana;
        const float* covf  = (const float*)cov;
        const float* muf   = (const float*)mu;
        for (int r = 0; r < rem; r++) {
            int row = ngroups_full * 4 + r;
            float accr = 0.f;
            #pragma unroll
            for (int i = 0; i < 5; i++) {
                float d = rrsf[row*5 + i] - rrspf[row*5 + i];
                accr += wtab[i] * d * d;
            }
            float rsum = 0.f, lens = 0.f;
            #pragma unroll
            for (int i = 0; i < 9; i++) {
                float d = predf[row*9 + i] - yobsf[row*9 + i];
                rsum += d * d;
                float z = nanf[row*9 + i];
                lens += (z == z) ? 1.f : 0.f;
            }
            float m0 = covf[row*9 + 0], m1 = covf[row*9 + 1], m2 = covf[row*9 + 2];
            float m3 = covf[row*9 + 3], m4 = covf[row*9 + 4], m5 = covf[row*9 + 5];
            float m6 = covf[row*9 + 6], m7 = covf[row*9 + 7], m8 = covf[row*9 + 8];
            float tr  = m0 + m4 + m8;
            float det = m0 * (m4*m8 - m5*m7)
                      - m1 * (m3*m8 - m5*m6)
                      + m2 * (m3*m7 - m4*m6);
            float accd = (LOGDET_SA - __logf(det)) + tr * INV49;
            float accm = 0.f;
            #pragma unroll
            for (int i = 0; i < 3; i++) {
                float d = muf[row*3 + i] - MU_PRIOR;
                accm += d * d;
            }
            tot += accr * s_rrs + __fdividef(rsum, lens) * s_obs
                 + accd * s_dk + accm * s_mu;
        }
    }

    // ---- block reduction ----
    __shared__ float warp_sums[8];
    #pragma unroll
    for (int o = 16; o > 0; o >>= 1) tot += __shfl_down_sync(0xffffffffu, tot, o);
    int lane = threadIdx.x & 31;
    int wid  = threadIdx.x >> 5;
    if (lane == 0) warp_sums[wid] = tot;
    __syncthreads();
    if (wid == 0) {
        int nw = blockDim.x >> 5;
        float v = (lane < nw) ? warp_sums[lane] : 0.f;
        #pragma unroll
        for (int o = 4; o > 0; o >>= 1) v += __shfl_down_sync(0xffffffffu, v, o);
        if (lane == 0) atomicAdd(out, v);
    }
}

extern "C" void kernel_launch(void* const* d_in, const int* in_sizes, int n_in,
                              void* d_out, int out_size)
{
    const float4* pred = (const float4*)d_in[0];
    const float4* yobs = (const float4*)d_in[1];
    const float4* rrs  = (const float4*)d_in[2];
    const float4* rrsp = (const float4*)d_in[3];
    const float4* nana = (const float4*)d_in[4];
    const float4* cov  = (const float4*)d_in[5];
    const float4* mu   = (const float4*)d_in[6];
    const float*  prm  = (const float*)d_in[7];
    float* out = (float*)d_out;

    int n  = in_sizes[0] / 9;
    int np = in_sizes[7];

    // write l2_norm term into out[0] (also initializes the poisoned output)
    init_out_kernel<<<1, 64>>>(prm, out, np);

    int ngroups = n / 4;
    int rem     = n % 4;
    int nthreads = ngroups + (rem ? 1 : 0);
    int block = 256;
    int grid  = (nthreads + block - 1) / block;

    double dn = (double)n;
    float s_rrs = (float)(1.0 / (5.0 * dn));
    float s_obs = (float)(10.0 / dn);
    float s_dk  = (float)(0.5 / dn);
    float s_mu  = (float)(0.5 / (4.9 * 3.0 * dn));

    loss_kernel<<<grid, block>>>(pred, yobs, rrs, rrsp, nana, cov, mu,
                                 out, ngroups, rem,
                                 s_rrs, s_obs, s_dk, s_mu);
}

// round 2
// speedup vs baseline: 1.0980x; 1.0980x over previous
#include <cuda_runtime.h>

// Single-pass, fully-coalesced streaming reduction.
// Each block stages 256 contiguous rows of the 9-wide arrays through smem
// (coalesced float4 GMEM loads), then does per-row math from smem
// (stride-9 float reads -> bank-conflict-free). Flat terms (rrs, mu) are
// streamed directly with contiguous float4 loads. One kernel; last block
// finalizes out[0] via device-global accumulator + counter (self-resetting
// so every graph replay is identical).

#define RPB 256
#define MU_PRIOR  0.6447f
#define LOGDET_SA 4.76770561517f   // 3*log(4.9)
#define INV49     (1.0f/4.9f)

#define W0 (1.0f/(0.0015f *0.0015f ))
#define W1 (1.0f/(0.0012f *0.0012f ))
#define W2 (1.0f/(0.001f  *0.001f  ))
#define W3 (1.0f/(0.00086f*0.00086f))
#define W4 (1.0f/(0.00057f*0.00057f))

__constant__ float c_W5[5] = {W0, W1, W2, W3, W4};
// c_W20[p*4+c] = W[(p+c)%5] : weights for a float4 whose first component has
// global-index-mod-5 == p
__constant__ float c_W20[20] = {
    W0, W1, W2, W3,
    W1, W2, W3, W4,
    W2, W3, W4, W0,
    W3, W4, W0, W1,
    W4, W0, W1, W2
};

__device__ float    g_partial = 0.f;
__device__ unsigned g_count   = 0u;

__global__ void __launch_bounds__(256)
loss_kernel(const float4* __restrict__ pred4, const float4* __restrict__ yobs4,
            const float4* __restrict__ rrs4,  const float4* __restrict__ rrsp4,
            const float4* __restrict__ nan4,  const float4* __restrict__ cov4,
            const float4* __restrict__ mu4,   const float*  __restrict__ prm,
            float* __restrict__ out,
            int n, int nblocks, int np,
            float s_rrs, float s_obs, float s_dk, float s_mu)
{
    __shared__ __align__(16) float s_dy2[RPB * 9];
    __shared__ __align__(16) float s_fin[RPB * 9];
    __shared__ __align__(16) float s_cov[RPB * 9];
    __shared__ float wsum[8];

    const int tid  = threadIdx.x;
    const int b    = blockIdx.x;
    const int row0 = b * RPB;
    const int rows = min(RPB, n - row0);

    float tot = 0.f;

    // ---------- flat rrs weighted SSQ (contiguous float4) ----------
    {
        const int base = row0 * 5;      // global float index (multiple of 4: 256*5*b)
        const int nf   = rows * 5;
        const int nv   = nf >> 2;
        const float4* a4 = rrs4  + (base >> 2);
        const float4* b4 = rrsp4 + (base >> 2);
        float acc = 0.f;
        for (int i = tid; i < nv; i += 256) {
            float4 a = a4[i];
            float4 bb = b4[i];
            int p = (int)((unsigned)(base + (i << 2)) % 5u);
            const float* w = &c_W20[p * 4];
            float d;
            d = a.x - bb.x; acc += w[0] * d * d;
            d = a.y - bb.y; acc += w[1] * d * d;
            d = a.z - bb.z; acc += w[2] * d * d;
            d = a.w - bb.w; acc += w[3] * d * d;
        }
        // scalar tail (only if rows*5 not divisible by 4)
        const float* af = (const float*)rrs4;
        const float* bf = (const float*)rrsp4;
        for (int g = base + (nv << 2) + tid; g < base + nf; g += 256) {
            float d = af[g] - bf[g];
            acc += c_W5[(unsigned)g % 5u] * d * d;
        }
        tot += acc * s_rrs;
    }

    // ---------- flat mu SSQ (contiguous float4) ----------
    {
        const int base = row0 * 3;
        const int nf   = rows * 3;
        const int nv   = nf >> 2;
        const float4* m4 = mu4 + (base >> 2);
        float acc = 0.f;
        for (int i = tid; i < nv; i += 256) {
            float4 m = m4[i];
            float d;
            d = m.x - MU_PRIOR; acc += d * d;
            d = m.y - MU_PRIOR; acc += d * d;
            d = m.z - MU_PRIOR; acc += d * d;
            d = m.w - MU_PRIOR; acc += d * d;
        }
        const float* mf = (const float*)mu4;
        for (int g = base + (nv << 2) + tid; g < base + nf; g += 256) {
            float d = mf[g] - MU_PRIOR;
            acc += d * d;
        }
        tot += acc * s_mu;
    }

    // ---------- stage 9-wide arrays coalesced -> smem ----------
    {
        const int base = row0 * 9;      // multiple of 4 (256*9*b)
        const int nf   = rows * 9;
        const int nv   = nf >> 2;
        const float4* p4 = pred4 + (base >> 2);
        const float4* q4 = yobs4 + (base >> 2);
        const float4* z4 = nan4  + (base >> 2);
        const float4* c4 = cov4  + (base >> 2);
        float4* sd4 = reinterpret_cast<float4*>(s_dy2);
        float4* sf4 = reinterpret_cast<float4*>(s_fin);
        float4* sc4 = reinterpret_cast<float4*>(s_cov);
        for (int i = tid; i < nv; i += 256) {
            float4 p = p4[i];
            float4 q = q4[i];
            float4 z = z4[i];
            float4 c = c4[i];
            float4 dsq, fin;
            float d;
            d = p.x - q.x; dsq.x = d * d; fin.x = (z.x == z.x) ? 1.f : 0.f;
            d = p.y - q.y; dsq.y = d * d; fin.y = (z.y == z.y) ? 1.f : 0.f;
            d = p.z - q.z; dsq.z = d * d; fin.z = (z.z == z.z) ? 1.f : 0.f;
            d = p.w - q.w; dsq.w = d * d; fin.w = (z.w == z.w) ? 1.f : 0.f;
            sd4[i] = dsq;
            sf4[i] = fin;
            sc4[i] = c;
        }
        const float* pf = (const float*)pred4;
        const float* qf = (const float*)yobs4;
        const float* zf = (const float*)nan4;
        const float* cf = (const float*)cov4;
        for (int j = (nv << 2) + tid; j < nf; j += 256) {
            float d = pf[base + j] - qf[base + j];
            s_dy2[j] = d * d;
            float z = zf[base + j];
            s_fin[j] = (z == z) ? 1.f : 0.f;
            s_cov[j] = cf[base + j];
        }
    }
    __syncthreads();

    // ---------- per-row math from smem (stride 9 -> conflict-free) ----------
    for (int r = tid; r < rows; r += 256) {
        const float* dy = &s_dy2[r * 9];
        const float* fi = &s_fin[r * 9];
        const float* cm = &s_cov[r * 9];

        float rsum = 0.f, lens = 0.f;
        #pragma unroll
        for (int i = 0; i < 9; i++) { rsum += dy[i]; lens += fi[i]; }
        tot += __fdividef(rsum, lens) * s_obs;

        float m0 = cm[0], m1 = cm[1], m2 = cm[2];
        float m3 = cm[3], m4 = cm[4], m5 = cm[5];
        float m6 = cm[6], m7 = cm[7], m8 = cm[8];
        float tr  = m0 + m4 + m8;
        float det = m0 * (m4 * m8 - m5 * m7)
                  - m1 * (m3 * m8 - m5 * m6)
                  + m2 * (m3 * m7 - m4 * m6);
        tot += ((LOGDET_SA - __logf(det)) + tr * INV49) * s_dk;
    }

    // ---------- params l2 (block 0 only) ----------
    if (b == 0) {
        float acc = 0.f;
        for (int i = tid; i < np; i += 256) {
            float d = prm[i] - 1.f;
            acc += d * d;
        }
        tot += acc / (float)np;
    }

    // ---------- block reduction ----------
    #pragma unroll
    for (int o = 16; o > 0; o >>= 1) tot += __shfl_down_sync(0xffffffffu, tot, o);
    int lane = tid & 31;
    int wid  = tid >> 5;
    if (lane == 0) wsum[wid] = tot;
    __syncthreads();
    if (wid == 0) {
        float v = (lane < 8) ? wsum[lane] : 0.f;
        #pragma unroll
        for (int o = 4; o > 0; o >>= 1) v += __shfl_down_sync(0xffffffffu, v, o);
        if (lane == 0) {
            atomicAdd(&g_partial, v);
            __threadfence();
            unsigned c = atomicAdd(&g_count, 1u);
            if (c == (unsigned)(nblocks - 1)) {
                __threadfence();
                float total = atomicExch(&g_partial, 0.f);  // read + reset for next replay
                out[0] = total;
                g_count = 0u;                                // reset for next replay
            }
        }
    }
}

extern "C" void kernel_launch(void* const* d_in, const int* in_sizes, int n_in,
                              void* d_out, int out_size)
{
    const float4* pred = (const float4*)d_in[0];
    const float4* yobs = (const float4*)d_in[1];
    const float4* rrs  = (const float4*)d_in[2];
    const float4* rrsp = (const float4*)d_in[3];
    const float4* nana = (const float4*)d_in[4];
    const float4* cov  = (const float4*)d_in[5];
    const float4* mu   = (const float4*)d_in[6];
    const float*  prm  = (const float*)d_in[7];
    float* out = (float*)d_out;

    int n  = in_sizes[0] / 9;
    int np = in_sizes[7];
    int nblocks = (n + RPB - 1) / RPB;

    double dn = (double)n;
    float s_rrs = (float)(1.0 / (5.0 * dn));
    float s_obs = (float)(10.0 / dn);
    float s_dk  = (float)(0.5 / dn);
    float s_mu  = (float)(0.5 / (4.9 * 3.0 * dn));

    loss_kernel<<<nblocks, 256>>>(pred, yobs, rrs, rrsp, nana, cov, mu, prm,
                                  out, n, nblocks, np,
                                  s_rrs, s_obs, s_dk, s_mu);
}